// round 1
// baseline (speedup 1.0000x reference)
#include <cuda_runtime.h>
#include <cuda_bf16.h>
#include <stdint.h>

// MinibatchDiscrimination fused kernel for GB300 (sm_103a)
// out[n, 0:256]  = x[n, :]                       (exact fp32 passthrough)
// out[n, 256+k1] = sum_d exp(-sum_k2 |M[n,k2,d]-M[n,k1,d]|),  M = x @ T
//
// Kernel 1: pack T (fp32 [256][512]) into bf16 mma-B-fragment order.
// Kernel 2: per 32-row tile: x->smem(bf16) + passthrough, mma.sync bf16 GEMM
//           into smem M, then warp-per-row pairwise L1 with packed f32x2 ops.

#define BM        32
#define NROWS     16384
#define FEAT      256
#define NCOLS     512      // NUM_KERNELS * KERNEL_DIM = 32*16
#define OUTC      288
#define XS_STRIDE 132      // uint32 (bf16x2) words per xs row: 128 data + 4 pad (conflict-free A-frag loads)
#define MS_STRIDE 516      // floats per Ms row: 512 data + 4 pad
#define SMEM_BYTES (BM*XS_STRIDE*4 + BM*MS_STRIDE*4)   // 16896 + 66048 = 82944

// Packed T fragments: [kiter(16)][ntpair(32)][lane(32)] -> uint4
//   .x/.y = B-frag regs (b0,b1) for n-tile 2*ntpair, .z/.w = for n-tile 2*ntpair+1
__device__ uint4 g_Tperm[16 * 32 * 32];

__global__ void convert_T_kernel(const float* __restrict__ T) {
    int tid  = blockIdx.x * blockDim.x + threadIdx.x;   // one thread per uint32 (65536 total)
    int j    = tid & 3;           // which u32 within the uint4
    int lane = (tid >> 2) & 31;
    int ntp  = (tid >> 7) & 31;   // n-tile pair index (global)
    int kit  = tid >> 12;         // k iteration (k0 = kit*16)
    int nt   = ntp * 2 + (j >> 1);   // global 8-col n-tile
    int rg   = j & 1;                // 0 -> b0 (k0+2tg), 1 -> b1 (k0+8+2tg)
    int gid  = lane >> 2, tg = lane & 3;
    int n    = nt * 8 + gid;
    int k    = kit * 16 + rg * 8 + tg * 2;
    __nv_bfloat162 v = __floats2bfloat162_rn(T[k * NCOLS + n], T[(k + 1) * NCOLS + n]);
    ((uint32_t*)g_Tperm)[tid] = *reinterpret_cast<uint32_t*>(&v);
}

__device__ __forceinline__ unsigned long long f2add(unsigned long long a, unsigned long long b) {
    unsigned long long r;
    asm("add.rn.f32x2 %0, %1, %2;" : "=l"(r) : "l"(a), "l"(b));
    return r;
}

#define MMA_BF16(c, a0, a1, a2, a3, b0, b1)                                   \
    asm volatile(                                                             \
        "mma.sync.aligned.m16n8k16.row.col.f32.bf16.bf16.f32 "                \
        "{%0,%1,%2,%3}, {%4,%5,%6,%7}, {%8,%9}, {%0,%1,%2,%3};"               \
        : "+f"(c[0]), "+f"(c[1]), "+f"(c[2]), "+f"(c[3])                      \
        : "r"(a0), "r"(a1), "r"(a2), "r"(a3), "r"(b0), "r"(b1))

__global__ __launch_bounds__(256, 2) void fused_kernel(const float* __restrict__ x,
                                                       float* __restrict__ out) {
    extern __shared__ char smem[];
    uint32_t* xs32 = (uint32_t*)smem;                    // [BM][XS_STRIDE] bf16x2 words
    float*    Ms   = (float*)(smem + BM * XS_STRIDE * 4); // [BM][MS_STRIDE]

    int rowbase = blockIdx.x * BM;
    int tid = threadIdx.x;

    // ---- Phase 1: load x tile, fp32 passthrough to out, bf16 into smem ----
    {
        const float4* xin = (const float4*)(x + (size_t)rowbase * FEAT);
        #pragma unroll
        for (int i = 0; i < 8; i++) {
            int f  = tid + i * 256;       // 0..2047 float4s (32 rows x 64)
            int r  = f >> 6, c4 = f & 63;
            float4 g = xin[r * 64 + c4];
            ((float4*)(out + (size_t)(rowbase + r) * OUTC))[c4] = g;
            __nv_bfloat162 p0 = __floats2bfloat162_rn(g.x, g.y);
            __nv_bfloat162 p1 = __floats2bfloat162_rn(g.z, g.w);
            xs32[r * XS_STRIDE + c4 * 2]     = *reinterpret_cast<uint32_t*>(&p0);
            xs32[r * XS_STRIDE + c4 * 2 + 1] = *reinterpret_cast<uint32_t*>(&p1);
        }
    }
    __syncthreads();

    int w = tid >> 5, lane = tid & 31;
    int gid = lane >> 2, tg = lane & 3;

    // ---- Phase 2: M[32][512] = x_tile @ T via mma.sync bf16 ----
    {
        int r0 = (w & 1) * 16;     // warp row tile (2-way split)
        int cw = (w >> 1);         // warp col tile 0..3 (128 cols each)
        float acc[16][4];
        #pragma unroll
        for (int i = 0; i < 16; i++) { acc[i][0] = acc[i][1] = acc[i][2] = acc[i][3] = 0.f; }

        #pragma unroll
        for (int kit = 0; kit < 16; kit++) {
            uint32_t a0 = xs32[(r0 + gid)     * XS_STRIDE + kit * 8 + tg];
            uint32_t a1 = xs32[(r0 + gid + 8) * XS_STRIDE + kit * 8 + tg];
            uint32_t a2 = xs32[(r0 + gid)     * XS_STRIDE + kit * 8 + 4 + tg];
            uint32_t a3 = xs32[(r0 + gid + 8) * XS_STRIDE + kit * 8 + 4 + tg];
            const uint4* tp = &g_Tperm[(kit * 32 + cw * 8) * 32 + lane];
            #pragma unroll
            for (int p = 0; p < 8; p++) {
                uint4 b = tp[p * 32];
                MMA_BF16(acc[2 * p],     a0, a1, a2, a3, b.x, b.y);
                MMA_BF16(acc[2 * p + 1], a0, a1, a2, a3, b.z, b.w);
            }
        }
        #pragma unroll
        for (int nt = 0; nt < 16; nt++) {
            int col = cw * 128 + nt * 8 + tg * 2;
            *(float2*)&Ms[(r0 + gid)     * MS_STRIDE + col] = make_float2(acc[nt][0], acc[nt][1]);
            *(float2*)&Ms[(r0 + gid + 8) * MS_STRIDE + col] = make_float2(acc[nt][2], acc[nt][3]);
        }
    }
    __syncthreads();

    // ---- Phase 3: pairwise L1 + exp. One warp per row, lane = k1. ----
    const unsigned long long SGN  = 0x8000000080000000ULL;
    const unsigned long long ABSM = 0x7FFFFFFF7FFFFFFFULL;
    #pragma unroll
    for (int rr = 0; rr < 4; rr++) {
        int n = w * 4 + rr;
        unsigned long long nv[8], ac[8];
        const unsigned long long* vr = (const unsigned long long*)&Ms[n * MS_STRIDE + lane * 16];
        #pragma unroll
        for (int j2 = 0; j2 < 8; j2++) { nv[j2] = vr[j2] ^ SGN; ac[j2] = 0ULL; }

        const unsigned long long* mr = (const unsigned long long*)&Ms[n * MS_STRIDE];
        #pragma unroll 4
        for (int k2 = 0; k2 < 32; k2++) {
            #pragma unroll
            for (int j2 = 0; j2 < 8; j2++) {
                unsigned long long t = f2add(mr[k2 * 8 + j2], nv[j2]);  // packed (M[k2,d] - M[k1,d])
                ac[j2] = f2add(ac[j2], t & ABSM);                        // packed += |diff|
            }
        }
        float s = 0.f;
        #pragma unroll
        for (int j2 = 0; j2 < 8; j2++) {
            s += __expf(-__uint_as_float((unsigned)(ac[j2] & 0xFFFFFFFFu)));
            s += __expf(-__uint_as_float((unsigned)(ac[j2] >> 32)));
        }
        out[(size_t)(rowbase + n) * OUTC + FEAT + lane] = s;
    }
}

extern "C" void kernel_launch(void* const* d_in, const int* in_sizes, int n_in,
                              void* d_out, int out_size) {
    const float* x = (const float*)d_in[0];
    const float* T = (const float*)d_in[1];
    float* out = (float*)d_out;

    convert_T_kernel<<<256, 256>>>(T);

    cudaFuncSetAttribute(fused_kernel, cudaFuncAttributeMaxDynamicSharedMemorySize, SMEM_BYTES);
    fused_kernel<<<NROWS / BM, 256, SMEM_BYTES>>>(x, out);
}